// round 1
// baseline (speedup 1.0000x reference)
#include <cuda_runtime.h>
#include <math.h>

#define HH 208
#define WW 336
#define NA 3
#define NPIX (HH*WW)            // 69888 per image
#define NPI (NPIX*NA)           // 209664 anchors per image
#define NB 2
#define PRE 2000
#define POST 1000
#define BBOX_CLIP 4.135166556742356f

// ---- output layout offsets (floats) ----
#define OFF_CLS   0
#define OFF_BBOX  (NB*NPIX*3)                // 419328
#define OFF_ROIS  (OFF_BBOX + NB*NPIX*12)    // 2096640
#define OFF_RSC   (OFF_ROIS + NB*POST*4)     // 2104640

// ---- device scratch (no cudaMalloc allowed) ----
__device__ float              g_scores[NB][NPI];
__device__ float4             g_boxes[NB][NPI];
__device__ unsigned int       g_hist[NB][256];
__device__ unsigned int       g_prefix[NB];
__device__ int                g_k[NB];
__device__ unsigned int       g_T[NB];
__device__ int                g_cntGT[NB];
__device__ int                g_cntEQ[NB];
__device__ unsigned long long g_gt[NB][2048];
__device__ unsigned long long g_eq[NB][4096];
__device__ float              g_pre_scores[NB][PRE];
__device__ float4             g_pre_boxes[NB][PRE];

// ============================================================
// K1: fused 1x1 convs + sigmoid + decode + clip
// warp-per-pixel; weights staged in smem as [256][15]
// ============================================================
__global__ void head_kernel(const float* __restrict__ feats,
                            const float* __restrict__ img_info,
                            const float* __restrict__ w_cls,
                            const float* __restrict__ b_cls,
                            const float* __restrict__ w_reg,
                            const float* __restrict__ b_reg,
                            float* __restrict__ out_cls,
                            float* __restrict__ out_bbox) {
    __shared__ float sw[256][15];   // cols 0..2 = cls, 3..14 = reg
    int tid = threadIdx.x;
    for (int i = tid; i < 256*15; i += blockDim.x) {
        int c = i / 15, o = i % 15;
        sw[c][o] = (o < 3) ? w_cls[c*3 + o] : w_reg[c*12 + (o-3)];
    }
    __syncthreads();

    int warp = tid >> 5, lane = tid & 31;
    int p = blockIdx.x * (blockDim.x >> 5) + warp;
    if (p >= NB*NPIX) return;
    int b  = p / NPIX;
    int hw = p % NPIX;

    const float* f = feats + (size_t)p * 256;
    float acc[15];
#pragma unroll
    for (int o = 0; o < 15; o++) acc[o] = 0.f;
#pragma unroll
    for (int k = 0; k < 8; k++) {
        int c = lane + 32*k;
        float fv = f[c];
#pragma unroll
        for (int o = 0; o < 15; o++) acc[o] = fmaf(fv, sw[c][o], acc[o]);
    }
#pragma unroll
    for (int o = 0; o < 15; o++) {
#pragma unroll
        for (int s = 16; s > 0; s >>= 1)
            acc[o] += __shfl_down_sync(0xffffffffu, acc[o], s);
    }

    if (lane == 0) {
        int h = hw / WW, w = hw % WW;
        float yc = (h + 0.5f) * 4.f;
        float xc = (w + 0.5f) * 4.f;
        float hmax = img_info[b*2 + 0];
        float wmax = img_info[b*2 + 1];
        const float axs[3] = {1.0f, 1.4f, 0.7f};
        const float ays[3] = {1.0f, 0.7f, 1.4f};
#pragma unroll
        for (int a = 0; a < 3; a++) {
            float cls = acc[a] + b_cls[a];
            out_cls[((size_t)b*NPIX + hw)*3 + a] = cls;
            float score = 1.f / (1.f + expf(-cls));
            int n = hw*3 + a;
            g_scores[b][n] = score;

            float dy = acc[3 + a*4 + 0] + b_reg[a*4 + 0];
            float dx = acc[3 + a*4 + 1] + b_reg[a*4 + 1];
            float dh = acc[3 + a*4 + 2] + b_reg[a*4 + 2];
            float dw = acc[3 + a*4 + 3] + b_reg[a*4 + 3];
            size_t bb = ((size_t)b*NPIX + hw)*12 + a*4;
            out_bbox[bb+0] = dy; out_bbox[bb+1] = dx;
            out_bbox[bb+2] = dh; out_bbox[bb+3] = dw;

            dh = fminf(fmaxf(dh, -BBOX_CLIP), BBOX_CLIP);
            dw = fminf(fmaxf(dw, -BBOX_CLIP), BBOX_CLIP);
            float ah = 32.f * ays[a], aw = 32.f * axs[a];
            float cy = dy*ah + yc, cx = dx*aw + xc;
            float hh2 = expf(dh)*ah, ww2 = expf(dw)*aw;
            float y1 = fminf(fmaxf(cy - 0.5f*hh2, 0.f), hmax);
            float x1 = fminf(fmaxf(cx - 0.5f*ww2, 0.f), wmax);
            float y2 = fminf(fmaxf(cy + 0.5f*hh2, 0.f), hmax);
            float x2 = fminf(fmaxf(cx + 0.5f*ww2, 0.f), wmax);
            g_boxes[b][n] = make_float4(y1, x1, y2, x2);
        }
    }
}

// ============================================================
// K2: exact top-2000 per image via 4-level radix select on
// positive-float bit patterns (monotonic as uint)
// ============================================================
__global__ void rs_init() {
    int t = threadIdx.x;
    if (t < NB) { g_prefix[t] = 0; g_k[t] = PRE; g_cntGT[t] = 0; g_cntEQ[t] = 0; }
    for (int i = t; i < NB*256; i += blockDim.x) ((unsigned int*)g_hist)[i] = 0;
}

__global__ void rs_hist(int level) {
    __shared__ unsigned int sh[NB][256];
    int tid = threadIdx.x;
    for (int i = tid; i < NB*256; i += blockDim.x) ((unsigned int*)sh)[i] = 0;
    __syncthreads();
    int shift = 24 - 8*level;
    unsigned pf0 = g_prefix[0], pf1 = g_prefix[1];
    long long total = (long long)NB * NPI;
    for (long long e = (long long)blockIdx.x*blockDim.x + tid; e < total;
         e += (long long)gridDim.x*blockDim.x) {
        int b = (int)(e / NPI);
        int n = (int)(e % NPI);
        unsigned key = __float_as_uint(g_scores[b][n]);
        unsigned pf = b ? pf1 : pf0;
        bool ok = (level == 0) || ((key >> (shift + 8)) == pf);
        if (ok) atomicAdd(&sh[b][(key >> shift) & 255], 1u);
    }
    __syncthreads();
    for (int i = tid; i < NB*256; i += blockDim.x) {
        unsigned v = ((unsigned int*)sh)[i];
        if (v) atomicAdd(&((unsigned int*)g_hist)[i], v);
    }
}

__global__ void rs_scan(int level) {
    int b = threadIdx.x;
    if (b < NB) {
        int k = g_k[b];
        unsigned cum = 0;
        int bin = 255;
        for (; bin > 0; bin--) {
            unsigned h = g_hist[b][bin];
            if (cum + h >= (unsigned)k) break;
            cum += h;
        }
        g_prefix[b] = (g_prefix[b] << 8) | (unsigned)bin;
        g_k[b] = k - (int)cum;
        if (level == 3) g_T[b] = g_prefix[b];
    }
    __syncthreads();
    for (int i = threadIdx.x; i < NB*256; i += blockDim.x)
        ((unsigned int*)g_hist)[i] = 0;
}

__global__ void rs_compact() {
    int tid = threadIdx.x;
    long long total = (long long)NB * NPI;
    for (long long e = (long long)blockIdx.x*blockDim.x + tid; e < total;
         e += (long long)gridDim.x*blockDim.x) {
        int b = (int)(e / NPI);
        int n = (int)(e % NPI);
        unsigned key = __float_as_uint(g_scores[b][n]);
        unsigned T = g_T[b];
        if (key > T) {
            int p = atomicAdd(&g_cntGT[b], 1);
            if (p < 2048)
                g_gt[b][p] = ((unsigned long long)key << 32) | (unsigned)(~(unsigned)n);
        } else if (key == T) {
            int p = atomicAdd(&g_cntEQ[b], 1);
            if (p < 4096)
                g_eq[b][p] = ((unsigned long long)key << 32) | (unsigned)(~(unsigned)n);
        }
    }
}

// bitonic sort (descending) of 2048 composite keys -> exact top_k semantics
__global__ void rs_sort() {
    __shared__ unsigned long long s[2048];
    int b = blockIdx.x, tid = threadIdx.x;
    int G = min(g_cntGT[b], 2048);
    int E = min(g_cntEQ[b], 2048 - G);
    for (int i = tid; i < 2048; i += 1024) {
        unsigned long long v = 0ull;
        if (i < G) v = g_gt[b][i];
        else if (i < G + E) v = g_eq[b][i - G];
        s[i] = v;
    }
    __syncthreads();
    for (int ksz = 2; ksz <= 2048; ksz <<= 1) {
        for (int j = ksz >> 1; j > 0; j >>= 1) {
            for (int i = tid; i < 2048; i += 1024) {
                int ixj = i ^ j;
                if (ixj > i) {
                    bool desc = ((i & ksz) == 0);
                    unsigned long long a = s[i], c = s[ixj];
                    bool sw = desc ? (a < c) : (a > c);
                    if (sw) { s[i] = c; s[ixj] = a; }
                }
            }
            __syncthreads();
        }
    }
    for (int i = tid; i < PRE; i += 1024) {
        unsigned long long v = s[i];
        unsigned n = ~(unsigned)(v & 0xffffffffu);
        g_pre_scores[b][i] = __uint_as_float((unsigned)(v >> 32));
        g_pre_boxes[b][i]  = g_boxes[b][n];
    }
}

// ============================================================
// K3: greedy NMS == sorted-order suppression scan (exact)
// ============================================================
__global__ void nms_kernel(float* __restrict__ out_rois,
                           float* __restrict__ out_rscores) {
    __shared__ float4 sb[PRE];
    __shared__ unsigned char supp[PRE];
    __shared__ short kept[POST];
    int b = blockIdx.x, tid = threadIdx.x;
    for (int i = tid; i < PRE; i += 1024) { sb[i] = g_pre_boxes[b][i]; supp[i] = 0; }
    __syncthreads();

    int kc = 0;
    for (int j = 0; j < PRE && kc < POST; j++) {
        if (supp[j]) continue;        // uniform: all threads read same smem flag
        if (tid == 0) kept[kc] = (short)j;
        float4 bj = sb[j];
        float a1 = (bj.z - bj.x) * (bj.w - bj.y);
#pragma unroll
        for (int r = 0; r < 2; r++) {
            int i = tid + r*1024;
            if (i < PRE && !supp[i]) {
                float4 bi = sb[i];
                float y1 = fmaxf(bj.x, bi.x), x1 = fmaxf(bj.y, bi.y);
                float y2 = fminf(bj.z, bi.z), x2 = fminf(bj.w, bi.w);
                float inter = fmaxf(y2 - y1, 0.f) * fmaxf(x2 - x1, 0.f);
                float a2 = (bi.z - bi.x) * (bi.w - bi.y);
                float iou = inter / (a1 + a2 - inter + 1e-8f);
                if (iou > 0.7f) supp[i] = 1;
            }
        }
        kc++;
        __syncthreads();
    }
    __syncthreads();

    for (int i = tid; i < POST; i += 1024) {
        float4 bo; float sc;
        if (i < kc) { int j = kept[i]; bo = sb[j]; sc = g_pre_scores[b][j]; }
        else        { bo = sb[0]; sc = -1.f; }   // reference degenerate fill
        size_t o = ((size_t)b*POST + i) * 4;
        out_rois[o+0] = bo.x; out_rois[o+1] = bo.y;
        out_rois[o+2] = bo.z; out_rois[o+3] = bo.w;
        out_rscores[(size_t)b*POST + i] = sc;
    }
}

// ============================================================
extern "C" void kernel_launch(void* const* d_in, const int* in_sizes, int n_in,
                              void* d_out, int out_size) {
    const float* feats    = (const float*)d_in[0];
    const float* img_info = (const float*)d_in[1];
    const float* w_cls    = (const float*)d_in[2];
    const float* b_cls    = (const float*)d_in[3];
    const float* w_reg    = (const float*)d_in[4];
    const float* b_reg    = (const float*)d_in[5];
    float* out = (float*)d_out;

    float* out_cls  = out + OFF_CLS;
    float* out_bbox = out + OFF_BBOX;
    float* out_rois = out + OFF_ROIS;
    float* out_rsc  = out + OFF_RSC;

    // K1: 8 warps/block, one pixel per warp
    int pixels = NB * NPIX;                 // 139776
    int blocks = (pixels + 7) / 8;          // 17472
    head_kernel<<<blocks, 256>>>(feats, img_info, w_cls, b_cls, w_reg, b_reg,
                                 out_cls, out_bbox);

    // K2: radix select (4 levels of 8 bits)
    rs_init<<<1, 256>>>();
    for (int level = 0; level < 4; level++) {
        rs_hist<<<512, 256>>>(level);
        rs_scan<<<1, 256>>>(level);
    }
    rs_compact<<<512, 256>>>();
    rs_sort<<<NB, 1024>>>();

    // K3: NMS
    nms_kernel<<<NB, 1024>>>(out_rois, out_rsc);
}

// round 2
// speedup vs baseline: 2.7265x; 2.7265x over previous
#include <cuda_runtime.h>
#include <math.h>

#define HH 208
#define WW 336
#define NA 3
#define NPIX (HH*WW)            // 69888 per image
#define NPI (NPIX*NA)           // 209664 anchors per image
#define NB 2
#define PRE 2000
#define POST 1000
#define PRE_PAD 2048
#define BBOX_CLIP 4.135166556742356f

// ---- output layout offsets (floats) ----
#define OFF_CLS   0
#define OFF_BBOX  (NB*NPIX*3)                // 419328
#define OFF_ROIS  (OFF_BBOX + NB*NPIX*12)    // 2096640
#define OFF_RSC   (OFF_ROIS + NB*POST*4)     // 2104640

// ---- device scratch ----
__device__ float              g_scores[NB][NPI];
__device__ float4             g_boxes[NB][NPI];
__device__ float              g_pre_scores[NB][PRE_PAD];
__device__ float4             g_pre_boxes[NB][PRE_PAD];
__device__ unsigned long long g_mask[NB][PRE_PAD][32];   // 1 MB

// ============================================================
// K1: fused 1x1 convs + sigmoid + decode + clip
// warp-per-pixel; weights in smem as float4 swq[4][256] (conflict-free)
// ============================================================
__global__ void head_kernel(const float* __restrict__ feats,
                            const float* __restrict__ img_info,
                            const float* __restrict__ w_cls,
                            const float* __restrict__ b_cls,
                            const float* __restrict__ w_reg,
                            const float* __restrict__ b_reg,
                            float* __restrict__ out_cls,
                            float* __restrict__ out_bbox) {
    __shared__ float4 swq[4][256];   // swq[q][c] = w[c][4q..4q+3] (o<3 cls, 3..14 reg, 15 pad)
    int tid = threadIdx.x;
    for (int idx = tid; idx < 1024; idx += blockDim.x) {
        int q = idx >> 8, c = idx & 255;
        float v[4];
#pragma unroll
        for (int u = 0; u < 4; u++) {
            int o = q*4 + u;
            v[u] = (o < 3) ? w_cls[c*3 + o] : (o < 15 ? w_reg[c*12 + (o-3)] : 0.f);
        }
        swq[q][c] = make_float4(v[0], v[1], v[2], v[3]);
    }
    __syncthreads();

    int warp = tid >> 5, lane = tid & 31;
    int p = blockIdx.x * (blockDim.x >> 5) + warp;
    if (p >= NB*NPIX) return;
    int b  = p / NPIX;
    int hw = p % NPIX;

    const float* f = feats + (size_t)p * 256;
    float acc[15];
#pragma unroll
    for (int o = 0; o < 15; o++) acc[o] = 0.f;
#pragma unroll
    for (int k = 0; k < 8; k++) {
        int c = lane + 32*k;
        float fv = f[c];
        float4 w0 = swq[0][c], w1 = swq[1][c], w2 = swq[2][c], w3 = swq[3][c];
        acc[0]  = fmaf(fv, w0.x, acc[0]);  acc[1]  = fmaf(fv, w0.y, acc[1]);
        acc[2]  = fmaf(fv, w0.z, acc[2]);  acc[3]  = fmaf(fv, w0.w, acc[3]);
        acc[4]  = fmaf(fv, w1.x, acc[4]);  acc[5]  = fmaf(fv, w1.y, acc[5]);
        acc[6]  = fmaf(fv, w1.z, acc[6]);  acc[7]  = fmaf(fv, w1.w, acc[7]);
        acc[8]  = fmaf(fv, w2.x, acc[8]);  acc[9]  = fmaf(fv, w2.y, acc[9]);
        acc[10] = fmaf(fv, w2.z, acc[10]); acc[11] = fmaf(fv, w2.w, acc[11]);
        acc[12] = fmaf(fv, w3.x, acc[12]); acc[13] = fmaf(fv, w3.y, acc[13]);
        acc[14] = fmaf(fv, w3.z, acc[14]);
    }
#pragma unroll
    for (int o = 0; o < 15; o++) {
#pragma unroll
        for (int s = 16; s > 0; s >>= 1)
            acc[o] += __shfl_down_sync(0xffffffffu, acc[o], s);
    }

    if (lane == 0) {
        int h = hw / WW, w = hw % WW;
        float yc = (h + 0.5f) * 4.f;
        float xc = (w + 0.5f) * 4.f;
        float hmax = img_info[b*2 + 0];
        float wmax = img_info[b*2 + 1];
        const float axs[3] = {1.0f, 1.4f, 0.7f};
        const float ays[3] = {1.0f, 0.7f, 1.4f};
#pragma unroll
        for (int a = 0; a < 3; a++) {
            float cls = acc[a] + b_cls[a];
            out_cls[((size_t)b*NPIX + hw)*3 + a] = cls;
            float score = 1.f / (1.f + expf(-cls));
            int n = hw*3 + a;
            g_scores[b][n] = score;

            float dy = acc[3 + a*4 + 0] + b_reg[a*4 + 0];
            float dx = acc[3 + a*4 + 1] + b_reg[a*4 + 1];
            float dh = acc[3 + a*4 + 2] + b_reg[a*4 + 2];
            float dw = acc[3 + a*4 + 3] + b_reg[a*4 + 3];
            size_t bb = ((size_t)b*NPIX + hw)*12 + a*4;
            out_bbox[bb+0] = dy; out_bbox[bb+1] = dx;
            out_bbox[bb+2] = dh; out_bbox[bb+3] = dw;

            dh = fminf(fmaxf(dh, -BBOX_CLIP), BBOX_CLIP);
            dw = fminf(fmaxf(dw, -BBOX_CLIP), BBOX_CLIP);
            float ah = 32.f * ays[a], aw = 32.f * axs[a];
            float cy = dy*ah + yc, cx = dx*aw + xc;
            float hh2 = expf(dh)*ah, ww2 = expf(dw)*aw;
            float y1 = fminf(fmaxf(cy - 0.5f*hh2, 0.f), hmax);
            float x1 = fminf(fmaxf(cx - 0.5f*ww2, 0.f), wmax);
            float y2 = fminf(fmaxf(cy + 0.5f*hh2, 0.f), hmax);
            float x2 = fminf(fmaxf(cx + 0.5f*ww2, 0.f), wmax);
            g_boxes[b][n] = make_float4(y1, x1, y2, x2);
        }
    }
}

// ============================================================
// K2: fused exact top-2000 per image (radix select + compact +
// bitonic sort) — ONE kernel, 1 block per image, 1024 threads
// ============================================================
__global__ void __launch_bounds__(1024, 1) topk_kernel() {
    __shared__ unsigned int hist[256];
    __shared__ unsigned int s_prefix;
    __shared__ int s_k, s_cntG, s_cntE;
    __shared__ unsigned long long gt[PRE_PAD];
    __shared__ unsigned long long eq[PRE_PAD];

    int b = blockIdx.x, t = threadIdx.x;
    if (t == 0) { s_prefix = 0; s_k = PRE; s_cntG = 0; s_cntE = 0; }
    __syncthreads();

    // ---- 4-level radix select (8 bits per level) ----
    for (int level = 0; level < 4; level++) {
        if (t < 256) hist[t] = 0;
        __syncthreads();
        unsigned pf = s_prefix;
        int shift = 24 - 8*level;
        for (int e = t; e < NPI; e += 1024) {
            unsigned key = __float_as_uint(g_scores[b][e]);
            if (level == 0 || (key >> (shift + 8)) == pf)
                atomicAdd(&hist[(key >> shift) & 255], 1u);
        }
        __syncthreads();
        // inclusive suffix scan of hist (256 bins)
        for (int off = 1; off < 256; off <<= 1) {
            unsigned add = (t < 256 && t + off < 256) ? hist[t + off] : 0u;
            __syncthreads();
            if (t < 256) hist[t] += add;
            __syncthreads();
        }
        int kcur = s_k;
        __syncthreads();
        if (t < 256) {
            unsigned sufT = hist[t];
            unsigned sufN = (t < 255) ? hist[t + 1] : 0u;
            if (sufT >= (unsigned)kcur && sufN < (unsigned)kcur) {
                s_prefix = (pf << 8) | (unsigned)t;
                s_k = kcur - (int)sufN;
            }
        }
        __syncthreads();
    }
    unsigned T = s_prefix;

    // ---- compaction: keys > T and keys == T (composite desc-score / asc-index key) ----
    for (int e = t; e < NPI; e += 1024) {
        unsigned key = __float_as_uint(g_scores[b][e]);
        if (key > T) {
            int p = atomicAdd(&s_cntG, 1);
            if (p < PRE_PAD)
                gt[p] = ((unsigned long long)key << 32) | (unsigned)(~(unsigned)e);
        } else if (key == T) {
            int p = atomicAdd(&s_cntE, 1);
            if (p < PRE_PAD)
                eq[p] = ((unsigned long long)key << 32) | (unsigned)(~(unsigned)e);
        }
    }
    __syncthreads();
    int G = min(s_cntG, PRE_PAD);
    int E = min(s_cntE, PRE_PAD - G);
    for (int i = t; i < PRE_PAD; i += 1024)
        if (i >= G) gt[i] = (i < G + E) ? eq[i - G] : 0ull;
    __syncthreads();

    // ---- bitonic sort desc, 2048 elements, 1024 threads ----
    for (int ksz = 2; ksz <= PRE_PAD; ksz <<= 1) {
        for (int j = ksz >> 1; j > 0; j >>= 1) {
            int i = t;
            {
                int ixj = i ^ j;
                if (ixj > i) {
                    bool desc = ((i & ksz) == 0);
                    unsigned long long a = gt[i], c2 = gt[ixj];
                    bool sw = desc ? (a < c2) : (a > c2);
                    if (sw) { gt[i] = c2; gt[ixj] = a; }
                }
            }
            i = t + 1024;
            {
                int ixj = i ^ j;
                if (ixj > i) {
                    bool desc = ((i & ksz) == 0);
                    unsigned long long a = gt[i], c2 = gt[ixj];
                    bool sw = desc ? (a < c2) : (a > c2);
                    if (sw) { gt[i] = c2; gt[ixj] = a; }
                }
            }
            __syncthreads();
        }
    }

    // ---- write padded pre-NMS lists ----
    for (int i = t; i < PRE_PAD; i += 1024) {
        unsigned long long v = gt[i];
        unsigned n = ~(unsigned)(v & 0xffffffffull);
        float4 bo = make_float4(0.f, 0.f, 0.f, 0.f);
        float sc = 0.f;
        if (v != 0ull && n < NPI) { bo = g_boxes[b][n]; sc = __uint_as_float((unsigned)(v >> 32)); }
        g_pre_boxes[b][i]  = bo;
        g_pre_scores[b][i] = sc;
    }
}

// ============================================================
// K3: pairwise suppression mask (upper triangle of word-columns)
// block = (b, it, half): rows [it*64+half*32, +32) x words [it, 32)
// lanes share the word -> smem broadcast, conflict-free
// ============================================================
__global__ void mask_kernel() {
    __shared__ float4 jb[PRE_PAD];
    __shared__ float  ca[PRE_PAD];
    int blk = blockIdx.x;
    int b = blk >> 6;
    int r = blk & 63;
    int it = r >> 1;
    int half = r & 1;
    int t = threadIdx.x;

    for (int i = t; i < PRE_PAD; i += 256) {
        float4 bx = g_pre_boxes[b][i];
        jb[i] = bx;
        ca[i] = 0.41176470588f * (bx.z - bx.x) * (bx.w - bx.y);  // 0.7/1.7 * area
    }
    __syncthreads();

    int lane = t & 31;
    int i = it*64 + half*32 + lane;
    float4 bi = jb[i];
    float cai = ca[i] + 4.1176e-9f;   // folds the 1e-8 epsilon
    int nwords = 32 - it;
    for (int wq = t >> 5; wq < nwords; wq += 8) {
        int w = it + wq;
        int j0 = w * 64;
        unsigned long long m = 0;
#pragma unroll
        for (int bit = 0; bit < 64; bit++) {
            float4 bj = jb[j0 + bit];
            float y1 = fmaxf(bi.x, bj.x), x1 = fmaxf(bi.y, bj.y);
            float y2 = fminf(bi.z, bj.z), x2 = fminf(bi.w, bj.w);
            float inter = fmaxf(y2 - y1, 0.f) * fmaxf(x2 - x1, 0.f);
            if (inter > cai + ca[j0 + bit]) m |= (1ull << bit);
        }
        g_mask[b][i][w] = m;
    }
}

// ============================================================
// K4: chunked bitmask scan (exact greedy NMS order) + output
// 1 block per image, 256 threads, 32 chunk phases
// ============================================================
__global__ void nms_scan(float* __restrict__ out_rois,
                         float* __restrict__ out_rscores) {
    __shared__ unsigned long long removed[32];
    __shared__ unsigned long long sIntra[64];
    __shared__ unsigned long long partial[256];
    __shared__ short kept[POST];
    __shared__ int s_kc, s_k0, s_nk;

    int b = blockIdx.x, t = threadIdx.x;
    if (t < 32) removed[t] = 0ull;
    if (t == 0) s_kc = 0;

    for (int c = 0; c < 32; c++) {
        __syncthreads();
        if (s_kc >= POST) break;                 // uniform (smem broadcast)
        if (t < 64) sIntra[t] = g_mask[b][c*64 + t][c];
        __syncthreads();
        if (t == 0) {
            unsigned long long R = removed[c];
            int k = s_kc;
            s_k0 = k;
            int lim = min(64, 2000 - c*64);
#pragma unroll
            for (int bit = 0; bit < 64; bit++) {
                if (bit < lim && k < POST && !((R >> bit) & 1ull)) {
                    kept[k++] = (short)(c*64 + bit);
                    R |= sIntra[bit];
                }
            }
            s_kc = k;
            s_nk = k - s_k0;
        }
        __syncthreads();
        // batched OR of kept rows into future words (MLP-pipelined loads)
        int w = t & 31, g = t >> 5;
        unsigned long long acc = 0ull;
        if (w > c) {
            int nk = s_nk, k0 = s_k0;
            for (int rr = g; rr < nk; rr += 8)
                acc |= g_mask[b][(int)kept[k0 + rr]][w];
        }
        partial[t] = acc;
        __syncthreads();
        if (t < 32 && t > c) {
            unsigned long long v = removed[t];
#pragma unroll
            for (int g2 = 0; g2 < 8; g2++) v |= partial[g2*32 + t];
            removed[t] = v;
        }
    }
    __syncthreads();

    int kc = s_kc;
    for (int i = t; i < POST; i += 256) {
        float4 bo; float sc;
        if (i < kc) { int j = kept[i]; bo = g_pre_boxes[b][j]; sc = g_pre_scores[b][j]; }
        else        { bo = g_pre_boxes[b][0]; sc = -1.f; }    // reference degenerate fill
        size_t o = ((size_t)b*POST + i) * 4;
        out_rois[o+0] = bo.x; out_rois[o+1] = bo.y;
        out_rois[o+2] = bo.z; out_rois[o+3] = bo.w;
        out_rscores[(size_t)b*POST + i] = sc;
    }
}

// ============================================================
extern "C" void kernel_launch(void* const* d_in, const int* in_sizes, int n_in,
                              void* d_out, int out_size) {
    const float* feats    = (const float*)d_in[0];
    const float* img_info = (const float*)d_in[1];
    const float* w_cls    = (const float*)d_in[2];
    const float* b_cls    = (const float*)d_in[3];
    const float* w_reg    = (const float*)d_in[4];
    const float* b_reg    = (const float*)d_in[5];
    float* out = (float*)d_out;

    float* out_cls  = out + OFF_CLS;
    float* out_bbox = out + OFF_BBOX;
    float* out_rois = out + OFF_ROIS;
    float* out_rsc  = out + OFF_RSC;

    int pixels = NB * NPIX;                 // 139776
    int blocks = (pixels + 7) / 8;          // 17472
    head_kernel<<<blocks, 256>>>(feats, img_info, w_cls, b_cls, w_reg, b_reg,
                                 out_cls, out_bbox);

    topk_kernel<<<NB, 1024>>>();
    mask_kernel<<<NB*64, 256>>>();
    nms_scan<<<NB, 256>>>(out_rois, out_rsc);
}

// round 3
// speedup vs baseline: 3.4613x; 1.2695x over previous
#include <cuda_runtime.h>
#include <math.h>

#define HH 208
#define WW 336
#define NA 3
#define NPIX (HH*WW)            // 69888 per image
#define NPI (NPIX*NA)           // 209664 anchors per image
#define NB 2
#define PRE 2000
#define POST 1000
#define PRE_PAD 2048
#define SORT_N 4096
#define BBOX_CLIP 4.135166556742356f

// ---- output layout offsets (floats) ----
#define OFF_CLS   0
#define OFF_BBOX  (NB*NPIX*3)                // 419328
#define OFF_ROIS  (OFF_BBOX + NB*NPIX*12)    // 2096640
#define OFF_RSC   (OFF_ROIS + NB*POST*4)     // 2104640

// ---- device scratch ----
__device__ float              g_scores[NB][NPI];
__device__ float4             g_boxes[NB][NPI];
__device__ unsigned int       g_h16[NB][65536];     // zeroed at load; re-zeroed by scan_kernel each call
__device__ int                g_pivot[NB];
__device__ int                g_cntG[NB];
__device__ int                g_cntE[NB];
__device__ unsigned long long g_gt[NB][PRE_PAD];
__device__ unsigned long long g_eq[NB][PRE_PAD];
__device__ float              g_pre_scores[NB][PRE_PAD];
__device__ float4             g_pre_boxes[NB][PRE_PAD];
__device__ unsigned long long g_mask[NB][PRE_PAD][32];

// ============================================================
// K1: fused 1x1 convs + sigmoid + decode + clip + score histogram
// ============================================================
__global__ void head_kernel(const float* __restrict__ feats,
                            const float* __restrict__ img_info,
                            const float* __restrict__ w_cls,
                            const float* __restrict__ b_cls,
                            const float* __restrict__ w_reg,
                            const float* __restrict__ b_reg,
                            float* __restrict__ out_cls,
                            float* __restrict__ out_bbox) {
    __shared__ float4 swq[4][256];   // swq[q][c] = w[c][4q..4q+3]
    int tid = threadIdx.x;
    for (int idx = tid; idx < 1024; idx += blockDim.x) {
        int q = idx >> 8, c = idx & 255;
        float v[4];
#pragma unroll
        for (int u = 0; u < 4; u++) {
            int o = q*4 + u;
            v[u] = (o < 3) ? w_cls[c*3 + o] : (o < 15 ? w_reg[c*12 + (o-3)] : 0.f);
        }
        swq[q][c] = make_float4(v[0], v[1], v[2], v[3]);
    }
    __syncthreads();

    int warp = tid >> 5, lane = tid & 31;
    int p = blockIdx.x * (blockDim.x >> 5) + warp;
    if (p >= NB*NPIX) return;
    int b  = p / NPIX;
    int hw = p % NPIX;

    const float* f = feats + (size_t)p * 256;
    float acc[15];
#pragma unroll
    for (int o = 0; o < 15; o++) acc[o] = 0.f;
#pragma unroll
    for (int k = 0; k < 8; k++) {
        int c = lane + 32*k;
        float fv = f[c];
        float4 w0 = swq[0][c], w1 = swq[1][c], w2 = swq[2][c], w3 = swq[3][c];
        acc[0]  = fmaf(fv, w0.x, acc[0]);  acc[1]  = fmaf(fv, w0.y, acc[1]);
        acc[2]  = fmaf(fv, w0.z, acc[2]);  acc[3]  = fmaf(fv, w0.w, acc[3]);
        acc[4]  = fmaf(fv, w1.x, acc[4]);  acc[5]  = fmaf(fv, w1.y, acc[5]);
        acc[6]  = fmaf(fv, w1.z, acc[6]);  acc[7]  = fmaf(fv, w1.w, acc[7]);
        acc[8]  = fmaf(fv, w2.x, acc[8]);  acc[9]  = fmaf(fv, w2.y, acc[9]);
        acc[10] = fmaf(fv, w2.z, acc[10]); acc[11] = fmaf(fv, w2.w, acc[11]);
        acc[12] = fmaf(fv, w3.x, acc[12]); acc[13] = fmaf(fv, w3.y, acc[13]);
        acc[14] = fmaf(fv, w3.z, acc[14]);
    }
#pragma unroll
    for (int o = 0; o < 15; o++) {
#pragma unroll
        for (int s = 16; s > 0; s >>= 1)
            acc[o] += __shfl_down_sync(0xffffffffu, acc[o], s);
    }

    if (lane == 0) {
        int h = hw / WW, w = hw % WW;
        float yc = (h + 0.5f) * 4.f;
        float xc = (w + 0.5f) * 4.f;
        float hmax = img_info[b*2 + 0];
        float wmax = img_info[b*2 + 1];
        const float axs[3] = {1.0f, 1.4f, 0.7f};
        const float ays[3] = {1.0f, 0.7f, 1.4f};
#pragma unroll
        for (int a = 0; a < 3; a++) {
            float cls = acc[a] + b_cls[a];
            out_cls[((size_t)b*NPIX + hw)*3 + a] = cls;
            float score = 1.f / (1.f + expf(-cls));
            int n = hw*3 + a;
            g_scores[b][n] = score;
            atomicAdd(&g_h16[b][__float_as_uint(score) >> 16], 1u);

            float dy = acc[3 + a*4 + 0] + b_reg[a*4 + 0];
            float dx = acc[3 + a*4 + 1] + b_reg[a*4 + 1];
            float dh = acc[3 + a*4 + 2] + b_reg[a*4 + 2];
            float dw = acc[3 + a*4 + 3] + b_reg[a*4 + 3];
            size_t bb = ((size_t)b*NPIX + hw)*12 + a*4;
            out_bbox[bb+0] = dy; out_bbox[bb+1] = dx;
            out_bbox[bb+2] = dh; out_bbox[bb+3] = dw;

            dh = fminf(fmaxf(dh, -BBOX_CLIP), BBOX_CLIP);
            dw = fminf(fmaxf(dw, -BBOX_CLIP), BBOX_CLIP);
            float ah = 32.f * ays[a], aw = 32.f * axs[a];
            float cy = dy*ah + yc, cx = dx*aw + xc;
            float hh2 = expf(dh)*ah, ww2 = expf(dw)*aw;
            float y1 = fminf(fmaxf(cy - 0.5f*hh2, 0.f), hmax);
            float x1 = fminf(fmaxf(cx - 0.5f*ww2, 0.f), wmax);
            float y2 = fminf(fmaxf(cy + 0.5f*hh2, 0.f), hmax);
            float x2 = fminf(fmaxf(cx + 0.5f*ww2, 0.f), wmax);
            g_boxes[b][n] = make_float4(y1, x1, y2, x2);
        }
    }
}

// ============================================================
// K2: pivot-bin search over the 65536-bin histogram (1 block/image),
// then re-zero the histogram + counters for next call
// ============================================================
__global__ void __launch_bounds__(1024, 1) scan_kernel() {
    __shared__ unsigned int ssum[1024];
    int b = blockIdx.x, t = threadIdx.x;
    const uint4* hv4 = (const uint4*)g_h16[b];
    unsigned sum = 0;
#pragma unroll
    for (int i = 0; i < 16; i++) {
        uint4 v = hv4[t*16 + i];
        sum += v.x + v.y + v.z + v.w;
    }
    ssum[t] = sum;
    __syncthreads();
    // inclusive suffix scan over 1024 thread sums
    for (int off = 1; off < 1024; off <<= 1) {
        unsigned add = (t + off < 1024) ? ssum[t + off] : 0u;
        __syncthreads();
        ssum[t] += add;
        __syncthreads();
    }
    unsigned above = (t < 1023) ? ssum[t + 1] : 0u;
    if (ssum[t] >= (unsigned)PRE && above < (unsigned)PRE) {
        // walk my 64 bins downward to find pivot bin
        unsigned cum = above;
        int pivot = t*64;
        const unsigned* hb = g_h16[b] + t*64;
        for (int j = 63; j >= 0; j--) {
            cum += hb[j];
            if (cum >= (unsigned)PRE) { pivot = t*64 + j; break; }
        }
        g_pivot[b] = pivot;
        g_cntG[b] = 0;
        g_cntE[b] = 0;
    }
    __syncthreads();
    // re-zero histogram (invariant for next kernel_launch call)
    uint4 z = make_uint4(0u, 0u, 0u, 0u);
    uint4* hw4 = (uint4*)g_h16[b];
#pragma unroll
    for (int i = 0; i < 16; i++) hw4[t*16 + i] = z;
}

// ============================================================
// K3: grid-wide compaction of candidates (bin > P and bin == P)
// ============================================================
__global__ void compact_kernel() {
    int t = threadIdx.x;
    long long total = (long long)NB * NPI;
    for (long long e = (long long)blockIdx.x*blockDim.x + t; e < total;
         e += (long long)gridDim.x*blockDim.x) {
        int b = (int)(e / NPI);
        int n = (int)(e % NPI);
        unsigned key = __float_as_uint(g_scores[b][n]);
        int bin = (int)(key >> 16);
        int P = g_pivot[b];
        if (bin > P) {
            int p = atomicAdd(&g_cntG[b], 1);
            if (p < PRE_PAD)
                g_gt[b][p] = ((unsigned long long)key << 32) | (unsigned)(~(unsigned)n);
        } else if (bin == P) {
            int p = atomicAdd(&g_cntE[b], 1);
            if (p < PRE_PAD)
                g_eq[b][p] = ((unsigned long long)key << 32) | (unsigned)(~(unsigned)n);
        }
    }
}

// ============================================================
// K4: bitonic sort (desc) of <=4096 candidates, emit top-2048 list
// ============================================================
__global__ void __launch_bounds__(1024, 1) sort_kernel() {
    __shared__ unsigned long long s[SORT_N];
    int b = blockIdx.x, t = threadIdx.x;
    int G = min(g_cntG[b], PRE_PAD);
    int E = min(g_cntE[b], SORT_N - G);
    for (int i = t; i < SORT_N; i += 1024) {
        unsigned long long v = 0ull;
        if (i < G) v = g_gt[b][i];
        else if (i < G + E) v = g_eq[b][i - G];
        s[i] = v;
    }
    __syncthreads();
    for (int ksz = 2; ksz <= SORT_N; ksz <<= 1) {
        for (int j = ksz >> 1; j > 0; j >>= 1) {
#pragma unroll
            for (int r = 0; r < 4; r++) {
                int i = t + r*1024;
                int ixj = i ^ j;
                if (ixj > i) {
                    bool desc = ((i & ksz) == 0);
                    unsigned long long a = s[i], c2 = s[ixj];
                    bool sw = desc ? (a < c2) : (a > c2);
                    if (sw) { s[i] = c2; s[ixj] = a; }
                }
            }
            __syncthreads();
        }
    }
    for (int i = t; i < PRE_PAD; i += 1024) {
        unsigned long long v = s[i];
        unsigned n = ~(unsigned)(v & 0xffffffffull);
        float4 bo = make_float4(0.f, 0.f, 0.f, 0.f);
        float sc = 0.f;
        if (v != 0ull && n < NPI) { bo = g_boxes[b][n]; sc = __uint_as_float((unsigned)(v >> 32)); }
        g_pre_boxes[b][i]  = bo;
        g_pre_scores[b][i] = sc;
    }
}

// ============================================================
// K5: pairwise suppression mask (upper triangle of word-columns)
// ============================================================
__global__ void mask_kernel() {
    __shared__ float4 jb[PRE_PAD];
    __shared__ float  ca[PRE_PAD];
    int blk = blockIdx.x;
    int b = blk >> 6;
    int r = blk & 63;
    int it = r >> 1;
    int half = r & 1;
    int t = threadIdx.x;

    for (int i = t; i < PRE_PAD; i += 256) {
        float4 bx = g_pre_boxes[b][i];
        jb[i] = bx;
        ca[i] = 0.41176470588f * (bx.z - bx.x) * (bx.w - bx.y);  // 0.7/1.7 * area
    }
    __syncthreads();

    int lane = t & 31;
    int i = it*64 + half*32 + lane;
    float4 bi = jb[i];
    float cai = ca[i] + 4.1176e-9f;
    int nwords = 32 - it;
    for (int wq = t >> 5; wq < nwords; wq += 8) {
        int w = it + wq;
        int j0 = w * 64;
        unsigned long long m = 0;
#pragma unroll
        for (int bit = 0; bit < 64; bit++) {
            float4 bj = jb[j0 + bit];
            float y1 = fmaxf(bi.x, bj.x), x1 = fmaxf(bi.y, bj.y);
            float y2 = fminf(bi.z, bj.z), x2 = fminf(bi.w, bj.w);
            float inter = fmaxf(y2 - y1, 0.f) * fmaxf(x2 - x1, 0.f);
            if (inter > cai + ca[j0 + bit]) m |= (1ull << bit);
        }
        g_mask[b][i][w] = m;
    }
}

// ============================================================
// K6: chunked bitmask scan — 1024 threads, branch-free greedy select
// ============================================================
__global__ void __launch_bounds__(1024, 1) nms_scan(float* __restrict__ out_rois,
                                                    float* __restrict__ out_rscores) {
    __shared__ unsigned long long removed[32];
    __shared__ unsigned long long sIntra[64];
    __shared__ unsigned long long partial[32][33];
    __shared__ short kept[POST + 8];
    __shared__ int s_kc, s_k0, s_nk;

    int b = blockIdx.x, t = threadIdx.x;
    if (t < 32) removed[t] = 0ull;
    if (t == 0) s_kc = 0;

    for (int c = 0; c < 32; c++) {
        __syncthreads();
        if (s_kc >= POST) break;                       // uniform
        if (t < 64) sIntra[t] = g_mask[b][c*64 + t][c];
        __syncthreads();
        if (t == 0) {
            unsigned long long R = removed[c];
            int k = s_kc;
            s_k0 = k;
            int lim = min(64, PRE - c*64);
#pragma unroll
            for (int bit = 0; bit < 64; bit++) {
                int keep = (bit < lim) & (k < POST) & (int)(~(R >> bit) & 1ull);
                kept[k] = (short)(c*64 + bit);         // harmless when !keep (overwritten)
                R |= keep ? sIntra[bit] : 0ull;
                k += keep;
            }
            s_kc = k;
            s_nk = k - s_k0;
        }
        __syncthreads();
        int w = t & 31, g = t >> 5;
        unsigned long long acc = 0ull;
        int nk = s_nk, k0 = s_k0;
        if (w > c) {
            for (int rr = g; rr < nk; rr += 32)
                acc |= g_mask[b][(int)kept[k0 + rr]][w];
        }
        partial[g][w] = acc;
        __syncthreads();
        if (t < 32 && t > c) {
            unsigned long long v = removed[t];
#pragma unroll
            for (int g2 = 0; g2 < 32; g2++) v |= partial[g2][t];
            removed[t] = v;
        }
    }
    __syncthreads();

    int kc = s_kc;
    for (int i = t; i < POST; i += 1024) {
        float4 bo; float sc;
        if (i < kc) { int j = kept[i]; bo = g_pre_boxes[b][j]; sc = g_pre_scores[b][j]; }
        else        { bo = g_pre_boxes[b][0]; sc = -1.f; }
        size_t o = ((size_t)b*POST + i) * 4;
        out_rois[o+0] = bo.x; out_rois[o+1] = bo.y;
        out_rois[o+2] = bo.z; out_rois[o+3] = bo.w;
        out_rscores[(size_t)b*POST + i] = sc;
    }
}

// ============================================================
extern "C" void kernel_launch(void* const* d_in, const int* in_sizes, int n_in,
                              void* d_out, int out_size) {
    const float* feats    = (const float*)d_in[0];
    const float* img_info = (const float*)d_in[1];
    const float* w_cls    = (const float*)d_in[2];
    const float* b_cls    = (const float*)d_in[3];
    const float* w_reg    = (const float*)d_in[4];
    const float* b_reg    = (const float*)d_in[5];
    float* out = (float*)d_out;

    float* out_cls  = out + OFF_CLS;
    float* out_bbox = out + OFF_BBOX;
    float* out_rois = out + OFF_ROIS;
    float* out_rsc  = out + OFF_RSC;

    int pixels = NB * NPIX;                 // 139776
    int blocks = (pixels + 7) / 8;          // 17472
    head_kernel<<<blocks, 256>>>(feats, img_info, w_cls, b_cls, w_reg, b_reg,
                                 out_cls, out_bbox);

    scan_kernel<<<NB, 1024>>>();
    compact_kernel<<<512, 256>>>();
    sort_kernel<<<NB, 1024>>>();
    mask_kernel<<<NB*64, 256>>>();
    nms_scan<<<NB, 1024>>>(out_rois, out_rsc);
}

// round 4
// speedup vs baseline: 4.7718x; 1.3786x over previous
#include <cuda_runtime.h>
#include <math.h>

#define HH 208
#define WW 336
#define NA 3
#define NPIX (HH*WW)            // 69888 per image
#define NPI (NPIX*NA)           // 209664 anchors per image
#define NB 2
#define PRE 2000
#define POST 1000
#define PRE_PAD 2048
#define SORT_N 4096
#define BBOX_CLIP 4.135166556742356f

// ---- output layout offsets (floats) ----
#define OFF_CLS   0
#define OFF_BBOX  (NB*NPIX*3)                // 419328
#define OFF_ROIS  (OFF_BBOX + NB*NPIX*12)    // 2096640
#define OFF_RSC   (OFF_ROIS + NB*POST*4)     // 2104640

// ---- device scratch ----
__device__ float              g_scores[NB][NPI];
__device__ float4             g_boxes[NB][NPI];
__device__ unsigned int       g_h16[NB][65536];     // zeroed at load; re-zeroed by compact_kernel
__device__ int                g_pivot[NB];
__device__ int                g_cntG[NB];
__device__ int                g_cntE[NB];
__device__ unsigned long long g_gt[NB][PRE_PAD];
__device__ unsigned long long g_eq[NB][PRE_PAD];
__device__ float              g_pre_scores[NB][PRE_PAD];
__device__ float4             g_pre_boxes[NB][PRE_PAD];
__device__ unsigned long long g_mask[NB][PRE_PAD][32];

// ---- f32x2 packed-math macros (sm_103a FFMA2) ----
#define FMA2(d, a, b)   asm("fma.rn.f32x2 %0, %1, %2, %0;" : "+l"(d) : "l"(a), "l"(b))
#define PACK2(d, x)     asm("mov.b64 %0, {%1, %1};" : "=l"(d) : "r"(__float_as_uint(x)))
#define UNPACK2(lo, hi, d) do { unsigned _l, _h; \
    asm("mov.b64 {%0, %1}, %2;" : "=r"(_l), "=r"(_h) : "l"(d)); \
    lo = __uint_as_float(_l); hi = __uint_as_float(_h); } while (0)

// ============================================================
// K1: fused 1x1 convs + sigmoid + decode + clip + score histogram
// v2: transpose-staged smem, thread-per-pixel (2 pixels/thread),
// f32x2 FMAs, zero shuffles. 512 pixels/block, 273 blocks exact.
// ============================================================
#define TILE_P 512
#define PITCH  522              // 522 % 32 == 10 -> conflict-free store & load patterns

__global__ void __launch_bounds__(256) head_kernel(
        const float* __restrict__ feats,
        const float* __restrict__ img_info,
        const float* __restrict__ w_cls,
        const float* __restrict__ b_cls,
        const float* __restrict__ w_reg,
        const float* __restrict__ b_reg,
        float* __restrict__ out_cls,
        float* __restrict__ out_bbox) {
    __shared__ float sf[16 * PITCH];                 // 16 channels x 512 pixels (+pad)
    __shared__ __align__(16) float wsm[16 * 16];     // 16 channels x 16 outputs (15 real + pad)

    int t = threadIdx.x;
    int p0 = blockIdx.x * TILE_P;
    const float4* f4 = (const float4*)feats;

    unsigned long long accA[8], accB[8];
#pragma unroll
    for (int q = 0; q < 8; q++) { accA[q] = 0ull; accB[q] = 0ull; }

    for (int cc = 0; cc < 16; cc++) {
        __syncthreads();
        // stage 512 pixels x 16 channels, transposed (conflict-free, verified mod 32)
#pragma unroll
        for (int u = 0; u < 8; u++) {
            int idx = u*256 + t;
            int pl = idx >> 2, c4 = idx & 3;
            float4 v = f4[(size_t)(p0 + pl)*64 + cc*4 + c4];
            int cb = c4*4;
            sf[(cb+0)*PITCH + pl] = v.x;
            sf[(cb+1)*PITCH + pl] = v.y;
            sf[(cb+2)*PITCH + pl] = v.z;
            sf[(cb+3)*PITCH + pl] = v.w;
        }
        // stage weight chunk: 16 channels x 16 outputs
        {
            int ch = t >> 4, o = t & 15;
            int cg = cc*16 + ch;
            float wv = (o < 3) ? w_cls[cg*3 + o] : (o < 15 ? w_reg[cg*12 + (o-3)] : 0.f);
            wsm[ch*16 + o] = wv;
        }
        __syncthreads();

#pragma unroll
        for (int cl = 0; cl < 16; cl++) {
            float fA = sf[cl*PITCH + t];
            float fB = sf[cl*PITCH + t + 256];
            unsigned long long fa2, fb2;
            PACK2(fa2, fA); PACK2(fb2, fB);
            const ulonglong2* wrow = (const ulonglong2*)(wsm + cl*16);
            ulonglong2 w01 = wrow[0], w23 = wrow[1], w45 = wrow[2], w67 = wrow[3];
            FMA2(accA[0], fa2, w01.x); FMA2(accA[1], fa2, w01.y);
            FMA2(accA[2], fa2, w23.x); FMA2(accA[3], fa2, w23.y);
            FMA2(accA[4], fa2, w45.x); FMA2(accA[5], fa2, w45.y);
            FMA2(accA[6], fa2, w67.x); FMA2(accA[7], fa2, w67.y);
            FMA2(accB[0], fb2, w01.x); FMA2(accB[1], fb2, w01.y);
            FMA2(accB[2], fb2, w23.x); FMA2(accB[3], fb2, w23.y);
            FMA2(accB[4], fb2, w45.x); FMA2(accB[5], fb2, w45.y);
            FMA2(accB[6], fb2, w67.x); FMA2(accB[7], fb2, w67.y);
        }
    }

    // ---- epilogue: both pixels ----
    const float axs[3] = {1.0f, 1.4f, 0.7f};
    const float ays[3] = {1.0f, 0.7f, 1.4f};
#pragma unroll
    for (int px = 0; px < 2; px++) {
        int p = p0 + t + px*256;
        int b  = p / NPIX;
        int hw = p % NPIX;
        float f[16];
#pragma unroll
        for (int q = 0; q < 8; q++) {
            float lo, hi;
            UNPACK2(lo, hi, px ? accB[q] : accA[q]);
            f[2*q] = lo; f[2*q+1] = hi;
        }
        int h = hw / WW, w = hw % WW;
        float yc = (h + 0.5f) * 4.f;
        float xc = (w + 0.5f) * 4.f;
        float hmax = img_info[b*2 + 0];
        float wmax = img_info[b*2 + 1];
#pragma unroll
        for (int a = 0; a < 3; a++) {
            float cls = f[a] + b_cls[a];
            out_cls[((size_t)b*NPIX + hw)*3 + a] = cls;
            float score = 1.f / (1.f + expf(-cls));
            int n = hw*3 + a;
            g_scores[b][n] = score;
            atomicAdd(&g_h16[b][__float_as_uint(score) >> 16], 1u);

            float dy = f[3 + a*4 + 0] + b_reg[a*4 + 0];
            float dx = f[3 + a*4 + 1] + b_reg[a*4 + 1];
            float dh = f[3 + a*4 + 2] + b_reg[a*4 + 2];
            float dw = f[3 + a*4 + 3] + b_reg[a*4 + 3];
            size_t bb = ((size_t)b*NPIX + hw)*12 + a*4;
            out_bbox[bb+0] = dy; out_bbox[bb+1] = dx;
            out_bbox[bb+2] = dh; out_bbox[bb+3] = dw;

            dh = fminf(fmaxf(dh, -BBOX_CLIP), BBOX_CLIP);
            dw = fminf(fmaxf(dw, -BBOX_CLIP), BBOX_CLIP);
            float ah = 32.f * ays[a], aw = 32.f * axs[a];
            float cy = dy*ah + yc, cx = dx*aw + xc;
            float hh2 = expf(dh)*ah, ww2 = expf(dw)*aw;
            float y1 = fminf(fmaxf(cy - 0.5f*hh2, 0.f), hmax);
            float x1 = fminf(fmaxf(cx - 0.5f*ww2, 0.f), wmax);
            float y2 = fminf(fmaxf(cy + 0.5f*hh2, 0.f), hmax);
            float x2 = fminf(fmaxf(cx + 0.5f*ww2, 0.f), wmax);
            g_boxes[b][n] = make_float4(y1, x1, y2, x2);
        }
    }
}

// ============================================================
// K2: pivot-bin search over the 65536-bin histogram (read-only)
// ============================================================
__global__ void __launch_bounds__(1024, 1) scan_kernel() {
    __shared__ unsigned int ssum[1024];
    int b = blockIdx.x, t = threadIdx.x;
    const uint4* hv4 = (const uint4*)g_h16[b];
    unsigned sum = 0;
#pragma unroll
    for (int i = 0; i < 16; i++) {
        uint4 v = hv4[t*16 + i];
        sum += v.x + v.y + v.z + v.w;
    }
    ssum[t] = sum;
    __syncthreads();
    for (int off = 1; off < 1024; off <<= 1) {
        unsigned add = (t + off < 1024) ? ssum[t + off] : 0u;
        __syncthreads();
        ssum[t] += add;
        __syncthreads();
    }
    unsigned above = (t < 1023) ? ssum[t + 1] : 0u;
    if (ssum[t] >= (unsigned)PRE && above < (unsigned)PRE) {
        unsigned cum = above;
        int pivot = t*64;
        const unsigned* hb = g_h16[b] + t*64;
        for (int j = 63; j >= 0; j--) {
            cum += hb[j];
            if (cum >= (unsigned)PRE) { pivot = t*64 + j; break; }
        }
        g_pivot[b] = pivot;
        g_cntG[b] = 0;
        g_cntE[b] = 0;
    }
}

// ============================================================
// K3: grid-wide compaction + histogram re-zero (for next call)
// ============================================================
__global__ void compact_kernel() {
    int t = threadIdx.x;
    // re-zero histogram: 512 blocks * 256 threads == 2 * 65536 exactly
    int zid = blockIdx.x * 256 + t;
    g_h16[zid >> 16][zid & 65535] = 0;

    long long total = (long long)NB * NPI;
    for (long long e = (long long)blockIdx.x*blockDim.x + t; e < total;
         e += (long long)gridDim.x*blockDim.x) {
        int b = (int)(e / NPI);
        int n = (int)(e % NPI);
        unsigned key = __float_as_uint(g_scores[b][n]);
        int bin = (int)(key >> 16);
        int P = g_pivot[b];
        if (bin > P) {
            int p = atomicAdd(&g_cntG[b], 1);
            if (p < PRE_PAD)
                g_gt[b][p] = ((unsigned long long)key << 32) | (unsigned)(~(unsigned)n);
        } else if (bin == P) {
            int p = atomicAdd(&g_cntE[b], 1);
            if (p < PRE_PAD)
                g_eq[b][p] = ((unsigned long long)key << 32) | (unsigned)(~(unsigned)n);
        }
    }
}

// ============================================================
// K4: hybrid bitonic sort (desc) of 4096: regs + shfl + smem
// 1024 threads, 4 elements/thread, i = e*1024 + t
// ============================================================
__global__ void __launch_bounds__(1024, 1) sort_kernel() {
    __shared__ unsigned long long s[SORT_N];
    int b = blockIdx.x, t = threadIdx.x;
    int G = min(g_cntG[b], PRE_PAD);
    int E = min(g_cntE[b], SORT_N - G);

    unsigned long long v[4];
#pragma unroll
    for (int e = 0; e < 4; e++) {
        int i = e*1024 + t;
        unsigned long long val = 0ull;
        if (i < G) val = g_gt[b][i];
        else if (i < G + E) val = g_eq[b][i - G];
        v[e] = val;
    }

    for (int k = 2; k <= SORT_N; k <<= 1) {
        // in-thread passes (j = 2048, 1024)
#pragma unroll
        for (int j = 2048; j >= 1024; j >>= 1) {
            if (j < k) {
                int eo = j >> 10;
#pragma unroll
                for (int e = 0; e < 4; e++) {
                    if ((e & eo) == 0) {
                        int e2 = e | eo;
                        int i = e*1024 + t;
                        bool up = ((i & k) == 0);
                        unsigned long long a = v[e], c2 = v[e2];
                        v[e]  = up ? (a > c2 ? a : c2) : (a < c2 ? a : c2);
                        v[e2] = up ? (a > c2 ? c2 : a) : (a < c2 ? c2 : a);
                    }
                }
            }
        }
        // smem passes (j = 512..32)
#pragma unroll
        for (int j = 512; j >= 32; j >>= 1) {
            if (j < k) {
#pragma unroll
                for (int e = 0; e < 4; e++) s[e*1024 + t] = v[e];
                __syncthreads();
#pragma unroll
                for (int e = 0; e < 4; e++) {
                    int i = e*1024 + t;
                    unsigned long long o = s[i ^ j];
                    bool keepMax = (((i & k) == 0) != ((i & j) != 0));
                    unsigned long long a = v[e];
                    v[e] = keepMax ? (a > o ? a : o) : (a < o ? a : o);
                }
                __syncthreads();
            }
        }
        // shuffle passes (j = 16..1)
#pragma unroll
        for (int j = 16; j >= 1; j >>= 1) {
            if (j < k) {
#pragma unroll
                for (int e = 0; e < 4; e++) {
                    int i = e*1024 + t;
                    unsigned long long o = __shfl_xor_sync(0xffffffffu, v[e], j);
                    bool keepMax = (((i & k) == 0) != ((t & j) != 0));
                    unsigned long long a = v[e];
                    v[e] = keepMax ? (a > o ? a : o) : (a < o ? a : o);
                }
            }
        }
    }

    // first 2048 elements live in e = 0,1
#pragma unroll
    for (int e = 0; e < 2; e++) {
        int i = e*1024 + t;
        unsigned long long val = v[e];
        unsigned n = ~(unsigned)(val & 0xffffffffull);
        float4 bo = make_float4(0.f, 0.f, 0.f, 0.f);
        float sc = 0.f;
        if (val != 0ull && n < NPI) { bo = g_boxes[b][n]; sc = __uint_as_float((unsigned)(val >> 32)); }
        g_pre_boxes[b][i]  = bo;
        g_pre_scores[b][i] = sc;
    }
}

// ============================================================
// K5: pairwise suppression mask (upper triangle of word-columns)
// ============================================================
__global__ void mask_kernel() {
    __shared__ float4 jb[PRE_PAD];
    __shared__ float  ca[PRE_PAD];
    int blk = blockIdx.x;
    int b = blk >> 6;
    int r = blk & 63;
    int it = r >> 1;
    int half = r & 1;
    int t = threadIdx.x;

    for (int i = t; i < PRE_PAD; i += 256) {
        float4 bx = g_pre_boxes[b][i];
        jb[i] = bx;
        ca[i] = 0.41176470588f * (bx.z - bx.x) * (bx.w - bx.y);  // 0.7/1.7 * area
    }
    __syncthreads();

    int lane = t & 31;
    int i = it*64 + half*32 + lane;
    float4 bi = jb[i];
    float cai = ca[i] + 4.1176e-9f;
    int nwords = 32 - it;
    for (int wq = t >> 5; wq < nwords; wq += 8) {
        int w = it + wq;
        int j0 = w * 64;
        unsigned long long m = 0;
#pragma unroll
        for (int bit = 0; bit < 64; bit++) {
            float4 bj = jb[j0 + bit];
            float y1 = fmaxf(bi.x, bj.x), x1 = fmaxf(bi.y, bj.y);
            float y2 = fminf(bi.z, bj.z), x2 = fminf(bi.w, bj.w);
            float inter = fmaxf(y2 - y1, 0.f) * fmaxf(x2 - x1, 0.f);
            if (inter > cai + ca[j0 + bit]) m |= (1ull << bit);
        }
        g_mask[b][i][w] = m;
    }
}

// ============================================================
// K6: chunked bitmask scan — 1024 threads, branch-free greedy select
// ============================================================
__global__ void __launch_bounds__(1024, 1) nms_scan(float* __restrict__ out_rois,
                                                    float* __restrict__ out_rscores) {
    __shared__ unsigned long long removed[32];
    __shared__ unsigned long long sIntra[64];
    __shared__ unsigned long long partial[32][33];
    __shared__ short kept[POST + 8];
    __shared__ int s_kc, s_k0, s_nk;

    int b = blockIdx.x, t = threadIdx.x;
    if (t < 32) removed[t] = 0ull;
    if (t == 0) s_kc = 0;

    for (int c = 0; c < 32; c++) {
        __syncthreads();
        if (s_kc >= POST) break;                       // uniform
        if (t < 64) sIntra[t] = g_mask[b][c*64 + t][c];
        __syncthreads();
        if (t == 0) {
            unsigned long long R = removed[c];
            int k = s_kc;
            s_k0 = k;
            int lim = min(64, PRE - c*64);
#pragma unroll
            for (int bit = 0; bit < 64; bit++) {
                int keep = (bit < lim) & (k < POST) & (int)(~(R >> bit) & 1ull);
                kept[k] = (short)(c*64 + bit);
                R |= keep ? sIntra[bit] : 0ull;
                k += keep;
            }
            s_kc = k;
            s_nk = k - s_k0;
        }
        __syncthreads();
        int w = t & 31, g = t >> 5;
        unsigned long long acc = 0ull;
        int nk = s_nk, k0 = s_k0;
        if (w > c) {
            for (int rr = g; rr < nk; rr += 32)
                acc |= g_mask[b][(int)kept[k0 + rr]][w];
        }
        partial[g][w] = acc;
        __syncthreads();
        if (t < 32 && t > c) {
            unsigned long long vv = removed[t];
#pragma unroll
            for (int g2 = 0; g2 < 32; g2++) vv |= partial[g2][t];
            removed[t] = vv;
        }
    }
    __syncthreads();

    int kc = s_kc;
    for (int i = t; i < POST; i += 1024) {
        float4 bo; float sc;
        if (i < kc) { int j = kept[i]; bo = g_pre_boxes[b][j]; sc = g_pre_scores[b][j]; }
        else        { bo = g_pre_boxes[b][0]; sc = -1.f; }
        size_t o = ((size_t)b*POST + i) * 4;
        out_rois[o+0] = bo.x; out_rois[o+1] = bo.y;
        out_rois[o+2] = bo.z; out_rois[o+3] = bo.w;
        out_rscores[(size_t)b*POST + i] = sc;
    }
}

// ============================================================
extern "C" void kernel_launch(void* const* d_in, const int* in_sizes, int n_in,
                              void* d_out, int out_size) {
    const float* feats    = (const float*)d_in[0];
    const float* img_info = (const float*)d_in[1];
    const float* w_cls    = (const float*)d_in[2];
    const float* b_cls    = (const float*)d_in[3];
    const float* w_reg    = (const float*)d_in[4];
    const float* b_reg    = (const float*)d_in[5];
    float* out = (float*)d_out;

    float* out_cls  = out + OFF_CLS;
    float* out_bbox = out + OFF_BBOX;
    float* out_rois = out + OFF_ROIS;
    float* out_rsc  = out + OFF_RSC;

    // K1: 512 pixels/block, 273 blocks exactly
    head_kernel<<<(NB*NPIX)/TILE_P, 256>>>(feats, img_info, w_cls, b_cls, w_reg, b_reg,
                                           out_cls, out_bbox);

    scan_kernel<<<NB, 1024>>>();
    compact_kernel<<<512, 256>>>();
    sort_kernel<<<NB, 1024>>>();
    mask_kernel<<<NB*64, 256>>>();
    nms_scan<<<NB, 1024>>>(out_rois, out_rsc);
}

// round 5
// speedup vs baseline: 5.1872x; 1.0871x over previous
#include <cuda_runtime.h>
#include <math.h>

#define HH 208
#define WW 336
#define NA 3
#define NPIX (HH*WW)            // 69888 per image
#define NPI (NPIX*NA)           // 209664 anchors per image
#define NB 2
#define PRE 2000
#define POST 1000
#define PRE_PAD 2048
#define BBOX_CLIP 4.135166556742356f

// ---- output layout offsets (floats) ----
#define OFF_CLS   0
#define OFF_BBOX  (NB*NPIX*3)                // 419328
#define OFF_ROIS  (OFF_BBOX + NB*NPIX*12)    // 2096640
#define OFF_RSC   (OFF_ROIS + NB*POST*4)     // 2104640

// ---- device scratch ----
__device__ float              g_scores[NB][NPI];
__device__ float4             g_boxes[NB][NPI];
__device__ unsigned int       g_h16[NB][65536];     // zeroed at load; re-zeroed by compact_kernel
__device__ int                g_pivot[NB];
__device__ int                g_cntG[NB];
__device__ int                g_cntE[NB];
__device__ unsigned long long g_gt[NB][PRE_PAD];
__device__ unsigned long long g_eq[NB][PRE_PAD];
__device__ float              g_pre_scores[NB][PRE_PAD];
__device__ float4             g_pre_boxes[NB][PRE_PAD];
__device__ unsigned long long g_mask[NB][PRE_PAD][32];

// ---- f32x2 packed-math macros (sm_103a FFMA2) ----
#define FMA2(d, a, b)   asm("fma.rn.f32x2 %0, %1, %2, %0;" : "+l"(d) : "l"(a), "l"(b))
#define PACK2(d, x)     asm("mov.b64 %0, {%1, %1};" : "=l"(d) : "r"(__float_as_uint(x)))
#define UNPACK2(lo, hi, d) do { unsigned _l, _h; \
    asm("mov.b64 {%0, %1}, %2;" : "=r"(_l), "=r"(_h) : "l"(d)); \
    lo = __uint_as_float(_l); hi = __uint_as_float(_h); } while (0)

// ============================================================
// K1: fused 1x1 convs + sigmoid + decode + clip + score histogram
// ============================================================
#define TILE_P 512
#define PITCH  522              // conflict-free store & load patterns (mod 32)

__global__ void __launch_bounds__(256) head_kernel(
        const float* __restrict__ feats,
        const float* __restrict__ img_info,
        const float* __restrict__ w_cls,
        const float* __restrict__ b_cls,
        const float* __restrict__ w_reg,
        const float* __restrict__ b_reg,
        float* __restrict__ out_cls,
        float* __restrict__ out_bbox) {
    __shared__ float sf[16 * PITCH];
    __shared__ __align__(16) float wsm[16 * 16];

    int t = threadIdx.x;
    int p0 = blockIdx.x * TILE_P;
    const float4* f4 = (const float4*)feats;

    unsigned long long accA[8], accB[8];
#pragma unroll
    for (int q = 0; q < 8; q++) { accA[q] = 0ull; accB[q] = 0ull; }

    for (int cc = 0; cc < 16; cc++) {
        __syncthreads();
#pragma unroll
        for (int u = 0; u < 8; u++) {
            int idx = u*256 + t;
            int pl = idx >> 2, c4 = idx & 3;
            float4 v = f4[(size_t)(p0 + pl)*64 + cc*4 + c4];
            int cb = c4*4;
            sf[(cb+0)*PITCH + pl] = v.x;
            sf[(cb+1)*PITCH + pl] = v.y;
            sf[(cb+2)*PITCH + pl] = v.z;
            sf[(cb+3)*PITCH + pl] = v.w;
        }
        {
            int ch = t >> 4, o = t & 15;
            int cg = cc*16 + ch;
            float wv = (o < 3) ? w_cls[cg*3 + o] : (o < 15 ? w_reg[cg*12 + (o-3)] : 0.f);
            wsm[ch*16 + o] = wv;
        }
        __syncthreads();

#pragma unroll
        for (int cl = 0; cl < 16; cl++) {
            float fA = sf[cl*PITCH + t];
            float fB = sf[cl*PITCH + t + 256];
            unsigned long long fa2, fb2;
            PACK2(fa2, fA); PACK2(fb2, fB);
            const ulonglong2* wrow = (const ulonglong2*)(wsm + cl*16);
            ulonglong2 w01 = wrow[0], w23 = wrow[1], w45 = wrow[2], w67 = wrow[3];
            FMA2(accA[0], fa2, w01.x); FMA2(accA[1], fa2, w01.y);
            FMA2(accA[2], fa2, w23.x); FMA2(accA[3], fa2, w23.y);
            FMA2(accA[4], fa2, w45.x); FMA2(accA[5], fa2, w45.y);
            FMA2(accA[6], fa2, w67.x); FMA2(accA[7], fa2, w67.y);
            FMA2(accB[0], fb2, w01.x); FMA2(accB[1], fb2, w01.y);
            FMA2(accB[2], fb2, w23.x); FMA2(accB[3], fb2, w23.y);
            FMA2(accB[4], fb2, w45.x); FMA2(accB[5], fb2, w45.y);
            FMA2(accB[6], fb2, w67.x); FMA2(accB[7], fb2, w67.y);
        }
    }

    const float axs[3] = {1.0f, 1.4f, 0.7f};
    const float ays[3] = {1.0f, 0.7f, 1.4f};
#pragma unroll
    for (int px = 0; px < 2; px++) {
        int p = p0 + t + px*256;
        int b  = p / NPIX;
        int hw = p % NPIX;
        float f[16];
#pragma unroll
        for (int q = 0; q < 8; q++) {
            float lo, hi;
            UNPACK2(lo, hi, px ? accB[q] : accA[q]);
            f[2*q] = lo; f[2*q+1] = hi;
        }
        int h = hw / WW, w = hw % WW;
        float yc = (h + 0.5f) * 4.f;
        float xc = (w + 0.5f) * 4.f;
        float hmax = img_info[b*2 + 0];
        float wmax = img_info[b*2 + 1];
#pragma unroll
        for (int a = 0; a < 3; a++) {
            float cls = f[a] + b_cls[a];
            out_cls[((size_t)b*NPIX + hw)*3 + a] = cls;
            float score = 1.f / (1.f + expf(-cls));
            int n = hw*3 + a;
            g_scores[b][n] = score;
            atomicAdd(&g_h16[b][__float_as_uint(score) >> 16], 1u);

            float dy = f[3 + a*4 + 0] + b_reg[a*4 + 0];
            float dx = f[3 + a*4 + 1] + b_reg[a*4 + 1];
            float dh = f[3 + a*4 + 2] + b_reg[a*4 + 2];
            float dw = f[3 + a*4 + 3] + b_reg[a*4 + 3];
            size_t bb = ((size_t)b*NPIX + hw)*12 + a*4;
            out_bbox[bb+0] = dy; out_bbox[bb+1] = dx;
            out_bbox[bb+2] = dh; out_bbox[bb+3] = dw;

            dh = fminf(fmaxf(dh, -BBOX_CLIP), BBOX_CLIP);
            dw = fminf(fmaxf(dw, -BBOX_CLIP), BBOX_CLIP);
            float ah = 32.f * ays[a], aw = 32.f * axs[a];
            float cy = dy*ah + yc, cx = dx*aw + xc;
            float hh2 = expf(dh)*ah, ww2 = expf(dw)*aw;
            float y1 = fminf(fmaxf(cy - 0.5f*hh2, 0.f), hmax);
            float x1 = fminf(fmaxf(cx - 0.5f*ww2, 0.f), wmax);
            float y2 = fminf(fmaxf(cy + 0.5f*hh2, 0.f), hmax);
            float x2 = fminf(fmaxf(cx + 0.5f*ww2, 0.f), wmax);
            g_boxes[b][n] = make_float4(y1, x1, y2, x2);
        }
    }
}

// ============================================================
// K2: pivot-bin search (shfl hierarchical suffix scan, 2 barriers)
// ============================================================
__global__ void __launch_bounds__(1024, 1) scan_kernel() {
    __shared__ unsigned int wabove[32];
    int b = blockIdx.x, t = threadIdx.x;
    int lane = t & 31, warp = t >> 5;
    const uint4* hv4 = (const uint4*)g_h16[b];
    unsigned sum = 0;
#pragma unroll
    for (int i = 0; i < 16; i++) {
        uint4 v = hv4[t*16 + i];
        sum += v.x + v.y + v.z + v.w;
    }
    // inclusive suffix scan within warp
    unsigned suf = sum;
#pragma unroll
    for (int off = 1; off < 32; off <<= 1) {
        unsigned n = __shfl_down_sync(0xffffffffu, suf, off);
        if (lane + off < 32) suf += n;
    }
    if (lane == 0) wabove[warp] = suf;     // warp total
    __syncthreads();
    if (warp == 0) {
        unsigned ws = wabove[lane];
        unsigned wsuf = ws;
#pragma unroll
        for (int off = 1; off < 32; off <<= 1) {
            unsigned n = __shfl_down_sync(0xffffffffu, wsuf, off);
            if (lane + off < 32) wsuf += n;
        }
        wabove[lane] = wsuf - ws;          // sum of warps strictly after
    }
    __syncthreads();
    unsigned sufT = suf + wabove[warp];    // suffix over all 1024 threads
    unsigned above = sufT - sum;           // suffix starting at t+1
    if (sufT >= (unsigned)PRE && above < (unsigned)PRE) {
        unsigned cum = above;
        int pivot = t*64;
        const unsigned* hb = g_h16[b] + t*64;
        for (int j = 63; j >= 0; j--) {
            cum += hb[j];
            if (cum >= (unsigned)PRE) { pivot = t*64 + j; break; }
        }
        g_pivot[b] = pivot;
        g_cntG[b] = 0;
        g_cntE[b] = 0;
    }
}

// ============================================================
// K3: grid-wide compaction + histogram re-zero (for next call)
// ============================================================
__global__ void compact_kernel() {
    int t = threadIdx.x;
    int zid = blockIdx.x * 256 + t;        // 512*256 == 2*65536 exactly
    g_h16[zid >> 16][zid & 65535] = 0;

    long long total = (long long)NB * NPI;
    for (long long e = (long long)blockIdx.x*blockDim.x + t; e < total;
         e += (long long)gridDim.x*blockDim.x) {
        int b = (int)(e / NPI);
        int n = (int)(e % NPI);
        unsigned key = __float_as_uint(g_scores[b][n]);
        int bin = (int)(key >> 16);
        int P = g_pivot[b];
        if (bin > P) {
            int p = atomicAdd(&g_cntG[b], 1);
            if (p < PRE_PAD)
                g_gt[b][p] = ((unsigned long long)key << 32) | (unsigned)(~(unsigned)n);
        } else if (bin == P) {
            int p = atomicAdd(&g_cntE[b], 1);
            if (p < PRE_PAD)
                g_eq[b][p] = ((unsigned long long)key << 32) | (unsigned)(~(unsigned)n);
        }
    }
}

// ============================================================
// K4: parallel split sort. All gt keys > all eq keys by construction,
// so sort(gt) ++ sort(eq) is the full sorted candidate list.
// grid = NB*2 blocks; each block bitonic-sorts 2048 (2 elems/thread).
// ============================================================
__global__ void __launch_bounds__(1024, 1) sort_kernel() {
    __shared__ unsigned long long s[PRE_PAD];
    int blk = blockIdx.x;
    int b = blk >> 1, part = blk & 1;
    int t = threadIdx.x;

    int G = min(g_cntG[b], PRE_PAD);
    int cnt = part ? min(g_cntE[b], PRE_PAD) : G;
    const unsigned long long* src = part ? g_eq[b] : g_gt[b];

    unsigned long long v[2];
#pragma unroll
    for (int e = 0; e < 2; e++) {
        int i = e*1024 + t;
        v[e] = (i < cnt) ? src[i] : 0ull;
    }

    for (int k = 2; k <= PRE_PAD; k <<= 1) {
        // in-register pass j = 1024 (only when k == 2048; up == true everywhere)
        if (k == PRE_PAD) {
            unsigned long long a = v[0], c2 = v[1];
            v[0] = a > c2 ? a : c2;
            v[1] = a > c2 ? c2 : a;
        }
        // smem passes j = 512..32
#pragma unroll
        for (int j = 512; j >= 32; j >>= 1) {
            if (j < k) {
#pragma unroll
                for (int e = 0; e < 2; e++) s[e*1024 + t] = v[e];
                __syncthreads();
#pragma unroll
                for (int e = 0; e < 2; e++) {
                    int i = e*1024 + t;
                    unsigned long long o = s[i ^ j];
                    bool keepMax = (((i & k) == 0) != ((i & j) != 0));
                    unsigned long long a = v[e];
                    v[e] = keepMax ? (a > o ? a : o) : (a < o ? a : o);
                }
                __syncthreads();
            }
        }
        // shuffle passes j = 16..1
#pragma unroll
        for (int j = 16; j >= 1; j >>= 1) {
            if (j < k) {
#pragma unroll
                for (int e = 0; e < 2; e++) {
                    int i = e*1024 + t;
                    unsigned long long o = __shfl_xor_sync(0xffffffffu, v[e], j);
                    bool keepMax = (((i & k) == 0) != ((t & j) != 0));
                    unsigned long long a = v[e];
                    v[e] = keepMax ? (a > o ? a : o) : (a < o ? a : o);
                }
            }
        }
    }

    // part 0 -> pre[0..G);  part 1 -> pre[G..2048) from eq_sorted[0..2048-G)
#pragma unroll
    for (int e = 0; e < 2; e++) {
        int i = e*1024 + t;
        int dst = part ? (G + i) : i;
        bool valid = part ? (dst < PRE_PAD) : (i < G);
        if (valid) {
            unsigned long long val = v[e];
            unsigned n = ~(unsigned)(val & 0xffffffffull);
            float4 bo = make_float4(0.f, 0.f, 0.f, 0.f);
            float sc = 0.f;
            if (val != 0ull && n < NPI) { bo = g_boxes[b][n]; sc = __uint_as_float((unsigned)(val >> 32)); }
            g_pre_boxes[b][dst]  = bo;
            g_pre_scores[b][dst] = sc;
        }
    }
}

// ============================================================
// K5: pairwise suppression mask (upper triangle of word-columns)
// ============================================================
__global__ void mask_kernel() {
    __shared__ float4 jb[PRE_PAD];
    __shared__ float  ca[PRE_PAD];
    int blk = blockIdx.x;
    int b = blk >> 6;
    int r = blk & 63;
    int it = r >> 1;
    int half = r & 1;
    int t = threadIdx.x;

    for (int i = t; i < PRE_PAD; i += 256) {
        float4 bx = g_pre_boxes[b][i];
        jb[i] = bx;
        ca[i] = 0.41176470588f * (bx.z - bx.x) * (bx.w - bx.y);  // 0.7/1.7 * area
    }
    __syncthreads();

    int lane = t & 31;
    int i = it*64 + half*32 + lane;
    float4 bi = jb[i];
    float cai = ca[i] + 4.1176e-9f;
    int nwords = 32 - it;
    for (int wq = t >> 5; wq < nwords; wq += 8) {
        int w = it + wq;
        int j0 = w * 64;
        unsigned long long m = 0;
#pragma unroll
        for (int bit = 0; bit < 64; bit++) {
            float4 bj = jb[j0 + bit];
            float y1 = fmaxf(bi.x, bj.x), x1 = fmaxf(bi.y, bj.y);
            float y2 = fminf(bi.z, bj.z), x2 = fminf(bi.w, bj.w);
            float inter = fmaxf(y2 - y1, 0.f) * fmaxf(x2 - x1, 0.f);
            if (inter > cai + ca[j0 + bit]) m |= (1ull << bit);
        }
        g_mask[b][i][w] = m;
    }
}

// ============================================================
// K6: chunked bitmask scan — prefetched register batches kill the
// dependent-LDS chain in the serial greedy loop
// ============================================================
__global__ void __launch_bounds__(1024, 1) nms_scan(float* __restrict__ out_rois,
                                                    float* __restrict__ out_rscores) {
    __shared__ unsigned long long removed[32];
    __shared__ unsigned long long sIntra[64];
    __shared__ unsigned long long partial[32][33];
    __shared__ short kept[POST + 8];
    __shared__ int s_kc, s_k0, s_nk;

    int b = blockIdx.x, t = threadIdx.x;
    if (t < 32) removed[t] = 0ull;
    if (t == 0) s_kc = 0;

    for (int c = 0; c < 32; c++) {
        __syncthreads();
        if (s_kc >= POST) break;                       // uniform
        if (t < 64) sIntra[t] = g_mask[b][c*64 + t][c];
        __syncthreads();
        if (t == 0) {
            unsigned long long R = removed[c];
            int k = s_kc;
            s_k0 = k;
            int lim = min(64, PRE - c*64);
#pragma unroll
            for (int base = 0; base < 64; base += 8) {
                unsigned long long si[8];
#pragma unroll
                for (int u = 0; u < 8; u++) si[u] = sIntra[base + u];   // batched MLP loads
#pragma unroll
                for (int u = 0; u < 8; u++) {
                    int bit = base + u;
                    int keep = (bit < lim) & (k < POST) & (int)(~(R >> bit) & 1ull);
                    kept[k] = (short)(c*64 + bit);
                    R |= keep ? si[u] : 0ull;
                    k += keep;
                }
            }
            s_kc = k;
            s_nk = k - s_k0;
        }
        __syncthreads();
        int w = t & 31, g = t >> 5;
        unsigned long long acc = 0ull;
        int nk = s_nk, k0 = s_k0;
        if (w > c) {
            for (int rr = g; rr < nk; rr += 32)
                acc |= g_mask[b][(int)kept[k0 + rr]][w];
        }
        partial[g][w] = acc;
        __syncthreads();
        if (t < 32 && t > c) {
            unsigned long long vv = removed[t];
#pragma unroll
            for (int g2 = 0; g2 < 32; g2++) vv |= partial[g2][t];
            removed[t] = vv;
        }
    }
    __syncthreads();

    int kc = s_kc;
    for (int i = t; i < POST; i += 1024) {
        float4 bo; float sc;
        if (i < kc) { int j = kept[i]; bo = g_pre_boxes[b][j]; sc = g_pre_scores[b][j]; }
        else        { bo = g_pre_boxes[b][0]; sc = -1.f; }
        size_t o = ((size_t)b*POST + i) * 4;
        out_rois[o+0] = bo.x; out_rois[o+1] = bo.y;
        out_rois[o+2] = bo.z; out_rois[o+3] = bo.w;
        out_rscores[(size_t)b*POST + i] = sc;
    }
}

// ============================================================
extern "C" void kernel_launch(void* const* d_in, const int* in_sizes, int n_in,
                              void* d_out, int out_size) {
    const float* feats    = (const float*)d_in[0];
    const float* img_info = (const float*)d_in[1];
    const float* w_cls    = (const float*)d_in[2];
    const float* b_cls    = (const float*)d_in[3];
    const float* w_reg    = (const float*)d_in[4];
    const float* b_reg    = (const float*)d_in[5];
    float* out = (float*)d_out;

    float* out_cls  = out + OFF_CLS;
    float* out_bbox = out + OFF_BBOX;
    float* out_rois = out + OFF_ROIS;
    float* out_rsc  = out + OFF_RSC;

    head_kernel<<<(NB*NPIX)/TILE_P, 256>>>(feats, img_info, w_cls, b_cls, w_reg, b_reg,
                                           out_cls, out_bbox);
    scan_kernel<<<NB, 1024>>>();
    compact_kernel<<<512, 256>>>();
    sort_kernel<<<NB*2, 1024>>>();
    mask_kernel<<<NB*64, 256>>>();
    nms_scan<<<NB, 1024>>>(out_rois, out_rsc);
}